// round 1
// baseline (speedup 1.0000x reference)
#include <cuda_runtime.h>
#include <math.h>

#define NC 10
#define NG 8

// Scratch (allocation-free rule: __device__ globals)
__device__ float g_colsum[NC * NG];
__device__ float g_count[NC];
__device__ float g_invS[NC * NG];
__device__ float g_logS[NC * NG];
__device__ float g_perclass[NC];

// ---------------------------------------------------------------------------
__global__ void k_zero() {
    int t = threadIdx.x;
    if (t < NC * NG) g_colsum[t] = 0.0f;
    if (t < NC) { g_count[t] = 0.0f; g_perclass[t] = 0.0f; }
}

// ---------------------------------------------------------------------------
// Pass 1: per-class column sums + counts.
// Each block owns ONE class; threads scan all labels, accumulate the 8 column
// sums for matching rows in registers (no per-row atomics).
__global__ __launch_bounds__(256) void k_pass1(const float* __restrict__ act,
                                               const int* __restrict__ labels,
                                               int N, int blocksPerClass) {
    const int c    = blockIdx.x / blocksPerClass;
    const int b    = blockIdx.x % blocksPerClass;
    const int tid  = b * blockDim.x + threadIdx.x;
    const int strd = blocksPerClass * blockDim.x;
    const int want = c + 1;

    float s0=0.f,s1=0.f,s2=0.f,s3=0.f,s4=0.f,s5=0.f,s6=0.f,s7=0.f,cnt=0.f;

    const int nq = N >> 2;
    const int4* lab4 = (const int4*)labels;

    for (int q = tid; q < nq; q += strd) {
        int4 lb = lab4[q];
        int n = q << 2;
        #define P1_DO(LV, OFF)                                                  \
            if ((LV) == want) {                                                 \
                const float4* r = (const float4*)(act +                         \
                        ((size_t)c * N + (size_t)(n + (OFF))) * NG);            \
                float4 a = r[0], bq = r[1];                                     \
                s0+=a.x; s1+=a.y; s2+=a.z; s3+=a.w;                             \
                s4+=bq.x; s5+=bq.y; s6+=bq.z; s7+=bq.w; cnt+=1.0f;              \
            }
        P1_DO(lb.x, 0) P1_DO(lb.y, 1) P1_DO(lb.z, 2) P1_DO(lb.w, 3)
        #undef P1_DO
    }
    // tail (N not multiple of 4)
    for (int n = (nq << 2) + tid; n < N; n += strd) {
        int lv = labels[n];
        if (lv == want) {
            const float4* r = (const float4*)(act + ((size_t)c * N + n) * NG);
            float4 a = r[0], bq = r[1];
            s0+=a.x; s1+=a.y; s2+=a.z; s3+=a.w;
            s4+=bq.x; s5+=bq.y; s6+=bq.z; s7+=bq.w; cnt+=1.0f;
        }
    }

    // warp tree-reduce 9 values
    #pragma unroll
    for (int o = 16; o > 0; o >>= 1) {
        s0 += __shfl_down_sync(0xFFFFFFFFu, s0, o);
        s1 += __shfl_down_sync(0xFFFFFFFFu, s1, o);
        s2 += __shfl_down_sync(0xFFFFFFFFu, s2, o);
        s3 += __shfl_down_sync(0xFFFFFFFFu, s3, o);
        s4 += __shfl_down_sync(0xFFFFFFFFu, s4, o);
        s5 += __shfl_down_sync(0xFFFFFFFFu, s5, o);
        s6 += __shfl_down_sync(0xFFFFFFFFu, s6, o);
        s7 += __shfl_down_sync(0xFFFFFFFFu, s7, o);
        cnt += __shfl_down_sync(0xFFFFFFFFu, cnt, o);
    }

    __shared__ float sh[NG + 1];
    if (threadIdx.x < NG + 1) sh[threadIdx.x] = 0.0f;
    __syncthreads();
    if ((threadIdx.x & 31) == 0) {
        atomicAdd(&sh[0], s0); atomicAdd(&sh[1], s1);
        atomicAdd(&sh[2], s2); atomicAdd(&sh[3], s3);
        atomicAdd(&sh[4], s4); atomicAdd(&sh[5], s5);
        atomicAdd(&sh[6], s6); atomicAdd(&sh[7], s7);
        atomicAdd(&sh[8], cnt);
    }
    __syncthreads();
    if (threadIdx.x < NG) atomicAdd(&g_colsum[c * NG + threadIdx.x], sh[threadIdx.x]);
    if (threadIdx.x == NG) atomicAdd(&g_count[c], sh[NG]);
}

// ---------------------------------------------------------------------------
__global__ void k_prep() {
    int t = threadIdx.x;
    if (t < NC * NG) {
        float S = g_colsum[t];
        g_invS[t] = 1.0f / S;
        g_logS[t] = __logf(S);
    }
}

// ---------------------------------------------------------------------------
// Pass 2: per row n with class c:
//   p_g  = a_g * invS[c,g]
//   lp_g = log(a_g) - logS[c,g]
//   contrib = (Sum p)(Sum lp) - Sum p*lp     -> per_class[c]
__global__ __launch_bounds__(256) void k_pass2(const float* __restrict__ act,
                                               const int* __restrict__ labels,
                                               int N) {
    __shared__ float s_inv[NC * NG];
    __shared__ float s_log[NC * NG];
    __shared__ float s_pc[NC];

    int t = threadIdx.x;
    if (t < NC * NG) { s_inv[t] = g_invS[t]; s_log[t] = g_logS[t]; }
    if (t < NC) s_pc[t] = 0.0f;
    __syncthreads();

    const int tid  = blockIdx.x * blockDim.x + t;
    const int strd = gridDim.x * blockDim.x;
    const int nq   = N >> 2;
    const int4* lab4 = (const int4*)labels;

    #define P2_DO(LV, NN)                                                       \
        if ((LV) >= 1) {                                                        \
            int c = (LV) - 1;                                                   \
            const float4* r = (const float4*)(act +                             \
                    ((size_t)c * N + (size_t)(NN)) * NG);                       \
            float4 a = r[0], bq = r[1];                                         \
            float av[NG] = {a.x, a.y, a.z, a.w, bq.x, bq.y, bq.z, bq.w};        \
            float P = 0.f, L = 0.f, PL = 0.f;                                   \
            _Pragma("unroll")                                                   \
            for (int g = 0; g < NG; ++g) {                                      \
                float p  = av[g] * s_inv[c * NG + g];                           \
                float lp = __logf(av[g]) - s_log[c * NG + g];                   \
                P += p; L += lp; PL = fmaf(p, lp, PL);                          \
            }                                                                   \
            atomicAdd(&s_pc[c], fmaf(P, L, -PL));                               \
        }

    for (int q = tid; q < nq; q += strd) {
        int4 lb = lab4[q];
        int n = q << 2;
        P2_DO(lb.x, n + 0) P2_DO(lb.y, n + 1) P2_DO(lb.z, n + 2) P2_DO(lb.w, n + 3)
    }
    for (int n = (nq << 2) + tid; n < N; n += strd) {
        int lv = labels[n];
        P2_DO(lv, n)
    }
    #undef P2_DO

    __syncthreads();
    if (t < NC) atomicAdd(&g_perclass[t], s_pc[t]);
}

// ---------------------------------------------------------------------------
__global__ void k_final(float* out) {
    if (threadIdx.x == 0) {
        float num = 0.0f, v = 0.0f;
        #pragma unroll
        for (int c = 0; c < NC; ++c) {
            if (g_count[c] >= 2.0f) { num += g_perclass[c]; v += 1.0f; }
        }
        out[0] = num / (v * (float)(NG * (NG - 1)));
    }
}

// ---------------------------------------------------------------------------
extern "C" void kernel_launch(void* const* d_in, const int* in_sizes, int n_in,
                              void* d_out, int out_size) {
    const float* act   = (const float*)d_in[0];   // [C, N, G] float32
    const int* labels  = (const int*)d_in[1];     // [N] int32
    const int N = in_sizes[1];

    k_zero<<<1, 128>>>();

    const int blocksPerClass = 120;
    k_pass1<<<NC * blocksPerClass, 256>>>(act, labels, N, blocksPerClass);

    k_prep<<<1, 128>>>();

    k_pass2<<<1184, 256>>>(act, labels, N);

    k_final<<<1, 32>>>((float*)d_out);
}

// round 2
// speedup vs baseline: 1.0267x; 1.0267x over previous
#include <cuda_runtime.h>
#include <math.h>

#define NC 10
#define NG 8

// Scratch (allocation-free rule: __device__ globals)
__device__ float g_S[NC * NG];     // col sums  S_i per class
__device__ float g_V[NC * NG];     // V_i = sum a*(R - log a) per class
__device__ float g_count[NC];

// ---------------------------------------------------------------------------
__global__ void k_zero() {
    int t = threadIdx.x;
    if (t < NC * NG) { g_S[t] = 0.0f; g_V[t] = 0.0f; }
    if (t < NC) g_count[t] = 0.0f;
}

// ---------------------------------------------------------------------------
// Single fused data pass. Each block owns ONE class; threads scan all labels
// and, on match, gather the 32B activation row and accumulate in registers:
//   S_i   += a_i
//   V_i   += a_i * (R - log a_i),  R = sum_j log a_j
//   count += 1
// No per-row atomics; one block-level reduction at the end.
__global__ __launch_bounds__(256) void k_fused(const float* __restrict__ act,
                                               const int* __restrict__ labels,
                                               int N, int blocksPerClass) {
    const int c    = blockIdx.x / blocksPerClass;
    const int b    = blockIdx.x % blocksPerClass;
    const int tid  = b * blockDim.x + threadIdx.x;
    const int strd = blocksPerClass * blockDim.x;
    const int want = c + 1;

    float s[NG] = {0,0,0,0,0,0,0,0};
    float v[NG] = {0,0,0,0,0,0,0,0};
    float cnt = 0.0f;

    const int nq = N >> 2;
    const int4* lab4 = (const int4*)labels;

    #define DO_ROW(NN)                                                          \
        {                                                                       \
            const float4* r = (const float4*)(act +                             \
                    ((size_t)c * N + (size_t)(NN)) * NG);                       \
            float4 aq = r[0], bq = r[1];                                        \
            float a[NG] = {aq.x, aq.y, aq.z, aq.w, bq.x, bq.y, bq.z, bq.w};     \
            float la[NG];                                                       \
            float R = 0.0f;                                                     \
            _Pragma("unroll")                                                   \
            for (int g = 0; g < NG; ++g) { la[g] = __logf(a[g]); R += la[g]; }  \
            _Pragma("unroll")                                                   \
            for (int g = 0; g < NG; ++g) {                                      \
                s[g] += a[g];                                                   \
                v[g] = fmaf(a[g], R - la[g], v[g]);                             \
            }                                                                   \
            cnt += 1.0f;                                                        \
        }

    for (int q = tid; q < nq; q += strd) {
        int4 lb = lab4[q];
        int n = q << 2;
        if (lb.x == want) DO_ROW(n + 0)
        if (lb.y == want) DO_ROW(n + 1)
        if (lb.z == want) DO_ROW(n + 2)
        if (lb.w == want) DO_ROW(n + 3)
    }
    for (int n = (nq << 2) + tid; n < N; n += strd) {
        if (labels[n] == want) DO_ROW(n)
    }
    #undef DO_ROW

    // warp tree-reduce 17 values
    #pragma unroll
    for (int o = 16; o > 0; o >>= 1) {
        #pragma unroll
        for (int g = 0; g < NG; ++g) {
            s[g] += __shfl_down_sync(0xFFFFFFFFu, s[g], o);
            v[g] += __shfl_down_sync(0xFFFFFFFFu, v[g], o);
        }
        cnt += __shfl_down_sync(0xFFFFFFFFu, cnt, o);
    }

    __shared__ float sh[2 * NG + 1];
    if (threadIdx.x < 2 * NG + 1) sh[threadIdx.x] = 0.0f;
    __syncthreads();
    if ((threadIdx.x & 31) == 0) {
        #pragma unroll
        for (int g = 0; g < NG; ++g) {
            atomicAdd(&sh[g], s[g]);
            atomicAdd(&sh[NG + g], v[g]);
        }
        atomicAdd(&sh[2 * NG], cnt);
    }
    __syncthreads();
    if (threadIdx.x < NG) {
        atomicAdd(&g_S[c * NG + threadIdx.x], sh[threadIdx.x]);
        atomicAdd(&g_V[c * NG + threadIdx.x], sh[NG + threadIdx.x]);
    }
    if (threadIdx.x == 2 * NG) atomicAdd(&g_count[c], sh[2 * NG]);
}

// ---------------------------------------------------------------------------
// per_class[c] = sum_i [ V_i/S_i - (G-1) * log S_i ];  answer = mean over
// valid classes (count >= 2) divided by G*(G-1).
__global__ void k_final(float* out) {
    __shared__ float pc[NC];
    int t = threadIdx.x;
    if (t < NC) pc[t] = 0.0f;
    __syncthreads();
    if (t < NC * NG) {
        int c = t / NG;
        float S = g_S[t];
        float term = g_V[t] / S - (float)(NG - 1) * logf(S);
        atomicAdd(&pc[c], term);
    }
    __syncthreads();
    if (t == 0) {
        float num = 0.0f, vcnt = 0.0f;
        #pragma unroll
        for (int c = 0; c < NC; ++c) {
            if (g_count[c] >= 2.0f) { num += pc[c]; vcnt += 1.0f; }
        }
        out[0] = num / (vcnt * (float)(NG * (NG - 1)));
    }
}

// ---------------------------------------------------------------------------
extern "C" void kernel_launch(void* const* d_in, const int* in_sizes, int n_in,
                              void* d_out, int out_size) {
    const float* act  = (const float*)d_in[0];   // [C, N, G] float32
    const int* labels = (const int*)d_in[1];     // [N] int32
    const int N = in_sizes[1];

    k_zero<<<1, 128>>>();

    const int blocksPerClass = 120;
    k_fused<<<NC * blocksPerClass, 256>>>(act, labels, N, blocksPerClass);

    k_final<<<1, 128>>>((float*)d_out);
}

// round 4
// speedup vs baseline: 1.7462x; 1.7008x over previous
#include <cuda_runtime.h>
#include <math.h>

#define NC 10
#define NG 8
#define TPB 256
#define WARPS (TPB / 32)
#define QCAP 256           // ring capacity per warp (power of 2)
#define BPC 60             // blocks per class

// Scratch (allocation-free rule: __device__ globals; zero-init at module load,
// k_final re-zeroes them so every graph replay starts clean).
__device__ float g_S[NC * NG];
__device__ float g_V[NC * NG];
__device__ float g_count[NC];

// ---------------------------------------------------------------------------
// Fused pass with warp-level compaction.
// Each block owns ONE class. Warps scan labels (int4, coalesced) with a
// WARP-UNIFORM loop bound (all 32 lanes execute every iteration; out-of-range
// lanes contribute label 0 which never matches want>=1), ballot-compact
// matched row indices into a shared ring, and process full 32-lane batches:
// unconditional 32B row gathers + full-utilization logf/FMA, accumulating
// S_i and V_i = sum a_i*(R - log a_i) in registers.
__global__ __launch_bounds__(TPB) void k_fused(const float* __restrict__ act,
                                               const int* __restrict__ labels,
                                               int N) {
    const int c    = blockIdx.x / BPC;
    const int b    = blockIdx.x % BPC;
    const int w    = threadIdx.x >> 5;
    const int lane = threadIdx.x & 31;
    const int want = c + 1;
    const size_t clsBase = (size_t)c * (size_t)N;

    __shared__ int qbuf[WARPS][QCAP];
    __shared__ float sh[2 * NG + 1];

    if (threadIdx.x < 2 * NG + 1) sh[threadIdx.x] = 0.0f;
    __syncthreads();

    float s[NG] = {0,0,0,0,0,0,0,0};
    float v[NG] = {0,0,0,0,0,0,0,0};

    unsigned head = 0, tail = 0;   // warp-uniform ring cursors

    const int nq = N >> 2;
    const int4* lab4 = (const int4*)labels;
    const int gw     = b * WARPS + w;          // global warp id within class
    const int warpsT = BPC * WARPS;
    const int stride = warpsT * 32;

    const unsigned ltmask = (1u << lane) - 1u;

    // Process one full batch of 32 queued rows (all lanes active).
    #define BATCH32()                                                           \
        {                                                                       \
            __syncwarp();                                                       \
            int idx = qbuf[w][(head + lane) & (QCAP - 1)];                      \
            head += 32;                                                         \
            const float4* r = (const float4*)(act + (clsBase + (size_t)idx) * NG); \
            float4 aq = r[0], bq = r[1];                                        \
            float a[NG] = {aq.x, aq.y, aq.z, aq.w, bq.x, bq.y, bq.z, bq.w};     \
            float la[NG]; float R = 0.0f;                                       \
            _Pragma("unroll")                                                   \
            for (int g = 0; g < NG; ++g) { la[g] = __logf(a[g]); R += la[g]; }  \
            _Pragma("unroll")                                                   \
            for (int g = 0; g < NG; ++g) {                                      \
                s[g] += a[g];                                                   \
                v[g] = fmaf(a[g], R - la[g], v[g]);                             \
            }                                                                   \
        }

    #define SLOT(LV, OFF)                                                      \
        {                                                                       \
            unsigned m = __ballot_sync(0xFFFFFFFFu, (LV) == want);              \
            if ((LV) == want)                                                   \
                qbuf[w][(tail + __popc(m & ltmask)) & (QCAP - 1)] = n + (OFF);  \
            tail += __popc(m);                                                  \
        }

    // Warp-uniform outer loop: 'base' is identical across the warp.
    for (int base = gw * 32; base < nq; base += stride) {
        int q = base + lane;
        int4 lb;
        if (q < nq) lb = lab4[q];
        else        { lb.x = 0; lb.y = 0; lb.z = 0; lb.w = 0; }
        int n = q << 2;
        SLOT(lb.x, 0) SLOT(lb.y, 1) SLOT(lb.z, 2) SLOT(lb.w, 3)
        while (tail - head >= 32) BATCH32()
    }

    // Scalar tail of labels (N % 4): warp 0 of block 0 per class, uniform loop.
    if (b == 0 && w == 0) {
        int tstart = nq << 2;
        for (int nb = tstart; nb < N; nb += 32) {
            int n = nb + lane;
            int lv = (n < N) ? labels[n] : 0;
            unsigned m = __ballot_sync(0xFFFFFFFFu, lv == want);
            if (lv == want)
                qbuf[w][(tail + __popc(m & ltmask)) & (QCAP - 1)] = n;
            tail += __popc(m);
            while (tail - head >= 32) BATCH32()
        }
    }

    // Drain remainder (<32) with predication (full warp executes).
    {
        unsigned rem = tail - head;
        __syncwarp();
        int idx = (lane < (int)rem) ? qbuf[w][(head + lane) & (QCAP - 1)] : 0;
        if (lane < (int)rem) {
            const float4* r = (const float4*)(act + (clsBase + (size_t)idx) * NG);
            float4 aq = r[0], bq = r[1];
            float a[NG] = {aq.x, aq.y, aq.z, aq.w, bq.x, bq.y, bq.z, bq.w};
            float la[NG]; float R = 0.0f;
            #pragma unroll
            for (int g = 0; g < NG; ++g) { la[g] = __logf(a[g]); R += la[g]; }
            #pragma unroll
            for (int g = 0; g < NG; ++g) {
                s[g] += a[g];
                v[g] = fmaf(a[g], R - la[g], v[g]);
            }
        }
    }
    #undef SLOT
    #undef BATCH32

    float cnt = (float)tail;   // warp-uniform: rows this warp enqueued

    // warp tree-reduce 16 values (full warp — all lanes alive here)
    #pragma unroll
    for (int o = 16; o > 0; o >>= 1) {
        #pragma unroll
        for (int g = 0; g < NG; ++g) {
            s[g] += __shfl_down_sync(0xFFFFFFFFu, s[g], o);
            v[g] += __shfl_down_sync(0xFFFFFFFFu, v[g], o);
        }
    }

    if (lane == 0) {
        #pragma unroll
        for (int g = 0; g < NG; ++g) {
            atomicAdd(&sh[g], s[g]);
            atomicAdd(&sh[NG + g], v[g]);
        }
        atomicAdd(&sh[2 * NG], cnt);
    }
    __syncthreads();
    if (threadIdx.x < NG) {
        atomicAdd(&g_S[c * NG + threadIdx.x], sh[threadIdx.x]);
        atomicAdd(&g_V[c * NG + threadIdx.x], sh[NG + threadIdx.x]);
    }
    if (threadIdx.x == 2 * NG) atomicAdd(&g_count[c], sh[2 * NG]);
}

// ---------------------------------------------------------------------------
// per_class[c] = sum_i [ V_i/S_i - (G-1) * log S_i ]; answer = mean over valid
// classes (count >= 2) / (G*(G-1)). Then reset scratch for the next replay.
__global__ void k_final(float* out) {
    __shared__ float pc[NC];
    int t = threadIdx.x;
    if (t < NC) pc[t] = 0.0f;
    __syncthreads();
    if (t < NC * NG) {
        int c = t / NG;
        float S = g_S[t];
        float term = g_V[t] / S - (float)(NG - 1) * logf(S);
        atomicAdd(&pc[c], term);
    }
    __syncthreads();
    if (t == 0) {
        float num = 0.0f, vcnt = 0.0f;
        #pragma unroll
        for (int c = 0; c < NC; ++c) {
            if (g_count[c] >= 2.0f) { num += pc[c]; vcnt += 1.0f; }
        }
        out[0] = num / (vcnt * (float)(NG * (NG - 1)));
    }
    __syncthreads();
    // reset scratch so the next replay starts from zeros (deterministic)
    if (t < NC * NG) { g_S[t] = 0.0f; g_V[t] = 0.0f; }
    if (t < NC) g_count[t] = 0.0f;
}

// ---------------------------------------------------------------------------
extern "C" void kernel_launch(void* const* d_in, const int* in_sizes, int n_in,
                              void* d_out, int out_size) {
    const float* act  = (const float*)d_in[0];   // [C, N, G] float32
    const int* labels = (const int*)d_in[1];     // [N] int32
    const int N = in_sizes[1];

    k_fused<<<NC * BPC, TPB>>>(act, labels, N);
    k_final<<<1, 128>>>((float*)d_out);
}